// round 6
// baseline (speedup 1.0000x reference)
#include <cuda_runtime.h>
#include <cuda_bf16.h>
#include <math.h>
#include <stdint.h>

#define S_LEN 40
#define T_LEN 30
#define BB    64
#define EMBD  620
#define HIDN  1000
#define ATTD  1000
#define MXO   500
#define OUTV  30000
#define G3    3000
#define E2    2000
#define DXK   2620
#define MXK   3620
#define MX2   1000

// ---------------- fp32 workspace ----------------
static const size_t O_EMB = 0;
static const size_t O_GXF = O_EMB + (size_t)S_LEN*BB*EMBD;
static const size_t O_GXB = O_GXF + (size_t)S_LEN*BB*G3;
static const size_t O_ENC = O_GXB + (size_t)S_LEN*BB*G3;
static const size_t O_EP  = O_ENC + (size_t)S_LEN*BB*E2;
static const size_t O_PA  = O_EP  + (size_t)S_LEN*BB*ATTD;
static const size_t O_PB  = O_PA  + (size_t)16*BB*G3;
static const size_t O_PM  = O_PB  + (size_t)8*BB*G3;
static const size_t O_HF  = O_PM  + (size_t)16*BB*MX2;
static const size_t O_HB  = O_HF  + (size_t)BB*HIDN;
static const size_t O_HD  = O_HB  + (size_t)BB*HIDN;
static const size_t O_X   = O_HD  + (size_t)BB*HIDN;
static const size_t O_MI  = O_X   + (size_t)BB*DXK;
static const size_t O_TM  = O_MI  + (size_t)BB*MXK;
static const size_t ARENA = O_TM  + (size_t)BB*MXO;

__device__ __align__(256) float g_ws[ARENA];
__device__ int g_inp[BB];

// ---------------- bf16 split-weight arena: W[N,K] -> [N, 3*Kp] = [h|m|l] ----
#define KP_EX  640
#define KP_WH  1024
#define KP_AWE 2048
#define KP_DWX 2624
#define KP_MXW 3648
#define KP_OUW 512

static const size_t WB_EXF = 0;
static const size_t WB_EXB = WB_EXF + (size_t)3000*3*KP_EX;
static const size_t WB_WHF = WB_EXB + (size_t)3000*3*KP_EX;
static const size_t WB_WHB = WB_WHF + (size_t)3000*3*KP_WH;
static const size_t WB_FC  = WB_WHB + (size_t)3000*3*KP_WH;
static const size_t WB_AWH = WB_FC  + (size_t)1000*3*KP_WH;
static const size_t WB_AWE = WB_AWH + (size_t)1000*3*KP_WH;
static const size_t WB_DWX = WB_AWE + (size_t)1000*3*KP_AWE;
static const size_t WB_DWH = WB_DWX + (size_t)3000*3*KP_DWX;
static const size_t WB_MXW = WB_DWH + (size_t)3000*3*KP_WH;
static const size_t WB_OUW = WB_MXW + (size_t)1000*3*KP_MXW;
static const size_t WB_TOT = WB_OUW + (size_t)30000*3*KP_OUW;

__device__ __align__(256) __nv_bfloat16 g_wb[WB_TOT];

// ---------------- PTX helpers (tcgen05 ones only referenced on sm_103a) ----
__device__ __forceinline__ uint32_t su32(const void* p)
{
    uint32_t a;
    asm("{ .reg .u64 t; cvta.to.shared.u64 t, %1; cvt.u32.u64 %0, t; }"
        : "=r"(a) : "l"(p));
    return a;
}
__device__ __forceinline__ uint64_t mkdesc(uint32_t addr)
{
    const uint64_t base = (uint64_t(2) << 61) | (uint64_t(1) << 46) |
                          (uint64_t(64) << 32) | (uint64_t(1) << 16);
    return base | ((uint64_t)(addr >> 4) & 0x3FFF);
}
__device__ __forceinline__ void mbar_init(uint32_t mb, uint32_t cnt)
{
    asm volatile("mbarrier.init.shared.b64 [%0], %1;" :: "r"(mb), "r"(cnt) : "memory");
}
__device__ __forceinline__ void mbar_wait(uint32_t mb, int parity)
{
    asm volatile(
        "{\n\t.reg .pred P;\n\t"
        "WL_%=:\n\t"
        "mbarrier.try_wait.parity.acquire.cta.shared::cta.b64 P, [%0], %1, 0x989680;\n\t"
        "@P bra.uni WD_%=;\n\t"
        "bra.uni WL_%=;\n\t"
        "WD_%=:\n\t}"
        :: "r"(mb), "r"(parity) : "memory");
}
__device__ __forceinline__ void mma_bf16_ss(uint32_t d, uint64_t ad, uint64_t bd,
                                            uint32_t idesc, uint32_t acc)
{
    asm volatile(
        "{\n\t.reg .pred p;\n\t"
        "setp.ne.u32 p, %5, 0;\n\t"
        "tcgen05.mma.cta_group::1.kind::f16 [%0], %1, %2, %3, {%4,%4,%4,%4}, p;\n\t}"
        :: "r"(d), "l"(ad), "l"(bd), "r"(idesc), "r"(0u), "r"(acc) : "memory");
}
__device__ __forceinline__ void tc_commit(uint32_t mb)
{
    asm volatile(
        "tcgen05.commit.cta_group::1.mbarrier::arrive::one.shared::cluster.b64 [%0];"
        :: "r"(mb) : "memory");
}
#define LDTM_X32(r, ta) \
    asm volatile( \
        "tcgen05.ld.sync.aligned.32x32b.x32.b32 " \
        "{%0,%1,%2,%3,%4,%5,%6,%7,%8,%9,%10,%11,%12,%13,%14,%15," \
        "%16,%17,%18,%19,%20,%21,%22,%23,%24,%25,%26,%27,%28,%29,%30,%31}, [%32];" \
        : "=r"((r)[0]),"=r"((r)[1]),"=r"((r)[2]),"=r"((r)[3]), \
          "=r"((r)[4]),"=r"((r)[5]),"=r"((r)[6]),"=r"((r)[7]), \
          "=r"((r)[8]),"=r"((r)[9]),"=r"((r)[10]),"=r"((r)[11]), \
          "=r"((r)[12]),"=r"((r)[13]),"=r"((r)[14]),"=r"((r)[15]), \
          "=r"((r)[16]),"=r"((r)[17]),"=r"((r)[18]),"=r"((r)[19]), \
          "=r"((r)[20]),"=r"((r)[21]),"=r"((r)[22]),"=r"((r)[23]), \
          "=r"((r)[24]),"=r"((r)[25]),"=r"((r)[26]),"=r"((r)[27]), \
          "=r"((r)[28]),"=r"((r)[29]),"=r"((r)[30]),"=r"((r)[31]) \
        : "r"(ta))

// idesc: F32 accum, BF16 A/B K-major, M=128, N=128
#define TG_IDESC 0x8200490u
// segment tables (seg 0..5 = hh,hm,mh,hl,lh,mm): A kind nibble, B part nibble
#define ASEG_TAB 0x120100u
#define BOFF_TAB 0x102010u

#define TG_SMEM 66560   // 1024 align slack + 4 * 16KB tiles

__device__ __forceinline__ unsigned short bf16seg(float a, int kind)
{
    __nv_bfloat16 h = __float2bfloat16(a);
    if (kind == 0) return __bfloat16_as_ushort(h);
    float r1 = a - __bfloat162float(h);
    __nv_bfloat16 m = __float2bfloat16(r1);
    if (kind == 1) return __bfloat16_as_ushort(m);
    float r2 = r1 - __bfloat162float(m);
    return __bfloat16_as_ushort(__float2bfloat16(r2));
}

// ---------------- weight conversion ----------------
__global__ void wconv_k(const float* __restrict__ W, int rs, int co,
                        __nv_bfloat16* __restrict__ Wb, int N, int K, int Kp)
{
    int i = blockIdx.x * blockDim.x + threadIdx.x;
    if (i >= N * Kp) return;
    int n = i / Kp, k = i - n * Kp;
    float a = (k < K) ? W[(size_t)n * rs + co + k] : 0.f;
    __nv_bfloat16 h = __float2bfloat16(a);
    float r1 = a - __bfloat162float(h);
    __nv_bfloat16 m = __float2bfloat16(r1);
    float r2 = r1 - __bfloat162float(m);
    __nv_bfloat16* row = Wb + (size_t)n * 3 * Kp;
    row[k] = h; row[Kp + k] = m; row[2 * Kp + k] = __float2bfloat16(r2);
}

// ---------------------------------------------------------------------------
// GEMM: C[M,N] = A[M,K]fp32 @ Wb[N,3Kp]^T, fp32 accumulation.
//  - sm_103a pass: tcgen05 path (6 bf16 split-segments, TMEM accum)
//  - sm_103 / host pass: SIMT fallback (weights reconstructed h+m+l)
// grid.z = split-K; partial z -> C + z*M*N; bias only when gridDim.z==1.
// dual=1: blockIdx.y picks arg set (M<=128); else blockIdx.y = M tile (128).
// ---------------------------------------------------------------------------
struct TG {
    const float* A; int lda; int K; int Kp;
    const __nv_bfloat16* Wb;
    const float* bias;
    float* C;
    int M, N, kc;   // kc in K'=6*Kp units (tcgen05 path), multiple of 64
};

__global__ void __launch_bounds__(128) tgemm_k(TG g0, TG g1, int dual)
{
    const TG g = (dual && blockIdx.y) ? g1 : g0;
    const int m0 = dual ? 0 : blockIdx.y * 128;
    const int n0 = blockIdx.x * 128;
    const int tid = threadIdx.x;

#if defined(__CUDA_ARCH_FEAT_SM103_ALL)
    // ======================= tcgen05 path (sm_103a) =======================
    const int Kp = g.Kp;
    const int K6 = 6 * Kp;
    int k0 = blockIdx.z * g.kc;
    int k1 = k0 + g.kc; if (k1 > K6) k1 = K6;
    const int nc = (k1 > k0) ? (k1 - k0) / 64 : 0;

    const int wid = tid >> 5;
    const int lane = tid & 31;

    extern __shared__ __align__(16) char dyn[];
    uint32_t dbase = (su32(dyn) + 1023u) & ~1023u;
    const uint32_t sA[2] = {dbase, dbase + 16384u};
    const uint32_t sB[2] = {dbase + 32768u, dbase + 49152u};

    __shared__ __align__(8) unsigned long long s_mbar[2];
    __shared__ uint32_t s_tptr;

    if (wid == 0) {
        asm volatile("tcgen05.alloc.cta_group::1.sync.aligned.shared::cta.b32 [%0], %1;"
                     :: "r"(su32(&s_tptr)), "r"(128u) : "memory");
        asm volatile("tcgen05.relinquish_alloc_permit.cta_group::1.sync.aligned;");
    }
    if (tid == 0) { mbar_init(su32(&s_mbar[0]), 1); mbar_init(su32(&s_mbar[1]), 1); }
    __syncthreads();
    const uint32_t tmem = s_tptr;

    int ph0 = 0, ph1 = 0;

    for (int i = 0; i < nc; i++) {
        const int buf = i & 1;
        const int ck = k0 + i * 64;
        const int seg = ck / Kp;
        const int kb = ck - seg * Kp;

        if (i >= 2) {
            if (buf == 0) { mbar_wait(su32(&s_mbar[0]), ph0); ph0 ^= 1; }
            else          { mbar_wait(su32(&s_mbar[1]), ph1); ph1 ^= 1; }
        }

        // stage A: 128 rows x 64 bf16, split-on-the-fly
        {
            const int akind = (ASEG_TAB >> (seg * 4)) & 0xF;
            const int gm = m0 + tid;
            const bool mv = gm < g.M;
            const float* Ap = g.A + (size_t)gm * g.lda + kb;
#pragma unroll
            for (int u = 0; u < 8; u++) {
                float f[8];
#pragma unroll
                for (int e = 0; e < 8; e += 4) {
                    int kk = kb + u * 8 + e;
                    if (mv && kk + 3 < g.K) {
                        float4 t = *(const float4*)(Ap + u * 8 + e);
                        f[e] = t.x; f[e+1] = t.y; f[e+2] = t.z; f[e+3] = t.w;
                    } else {
#pragma unroll
                        for (int q = 0; q < 4; q++)
                            f[e+q] = (mv && kk + q < g.K) ? Ap[u*8 + e + q] : 0.f;
                    }
                }
                unsigned short hb[8];
#pragma unroll
                for (int e = 0; e < 8; e++) hb[e] = bf16seg(f[e], akind);
                uint32_t w0 = (uint32_t)hb[0] | ((uint32_t)hb[1] << 16);
                uint32_t w1 = (uint32_t)hb[2] | ((uint32_t)hb[3] << 16);
                uint32_t w2 = (uint32_t)hb[4] | ((uint32_t)hb[5] << 16);
                uint32_t w3 = (uint32_t)hb[6] | ((uint32_t)hb[7] << 16);
                uint32_t off = tid * 128 + u * 16;
                uint32_t ad = sA[buf] + (off ^ ((off >> 3) & 0x70));
                asm volatile("st.shared.v4.b32 [%0], {%1,%2,%3,%4};"
                             :: "r"(ad), "r"(w0), "r"(w1), "r"(w2), "r"(w3) : "memory");
            }
        }
        // stage B: 128 rows x 64 bf16 from weight arena
        {
            const int bo = ((BOFF_TAB >> (seg * 4)) & 0xF) * Kp + kb;
            const int gn = n0 + tid;
            const __nv_bfloat16* Bp = g.Wb + (size_t)gn * 3 * Kp + bo;
            const bool nv = gn < g.N;
#pragma unroll
            for (int u = 0; u < 8; u++) {
                uint4 t = make_uint4(0, 0, 0, 0);
                if (nv) t = *(const uint4*)(Bp + u * 8);
                uint32_t off = tid * 128 + u * 16;
                uint32_t ad = sB[buf] + (off ^ ((off >> 3) & 0x70));
                asm volatile("st.shared.v4.b32 [%0], {%1,%2,%3,%4};"
                             :: "r"(ad), "r"(t.x), "r"(t.y), "r"(t.z), "r"(t.w) : "memory");
            }
        }
        asm volatile("fence.proxy.async.shared::cta;" ::: "memory");
        __syncthreads();

        if (tid == 0) {
            asm volatile("tcgen05.fence::after_thread_sync;" ::: "memory");
            uint64_t ad = mkdesc(sA[buf]);
            uint64_t bd = mkdesc(sB[buf]);
#pragma unroll
            for (int q = 0; q < 4; q++)
                mma_bf16_ss(tmem, ad + 2 * q, bd + 2 * q, TG_IDESC,
                            (i == 0 && q == 0) ? 0u : 1u);
            tc_commit(su32(&s_mbar[buf]));
        }
    }

    for (int t = (nc >= 2 ? nc - 2 : 0); t < nc; t++) {
        if ((t & 1) == 0) { mbar_wait(su32(&s_mbar[0]), ph0); ph0 ^= 1; }
        else              { mbar_wait(su32(&s_mbar[1]), ph1); ph1 ^= 1; }
    }
    asm volatile("tcgen05.fence::after_thread_sync;" ::: "memory");

    const bool fin = (gridDim.z == 1);
    float* Cz = g.C + (size_t)blockIdx.z * g.M * g.N;
    const int r = m0 + wid * 32 + lane;

    if (nc == 0) {
        if (r < g.M)
            for (int j = 0; j < 128; j++) {
                int c = n0 + j;
                if (c < g.N) Cz[(size_t)r * g.N + c] = (fin && g.bias) ? g.bias[c] : 0.f;
            }
    } else {
#pragma unroll
        for (int base = 0; base < 128; base += 32) {
            uint32_t regs[32];
            LDTM_X32(regs, tmem + base);
            asm volatile("tcgen05.wait::ld.sync.aligned;" ::: "memory");
            if (r < g.M) {
#pragma unroll
                for (int j = 0; j < 32; j++) {
                    int c = n0 + base + j;
                    if (c < g.N) {
                        float v = __uint_as_float(regs[j]);
                        if (fin && g.bias) v += g.bias[c];
                        Cz[(size_t)r * g.N + c] = v;
                    }
                }
            }
        }
    }

    __syncthreads();
    if (tid == 0) {
        asm volatile("mbarrier.inval.shared.b64 [%0];" :: "r"(su32(&s_mbar[0])) : "memory");
        asm volatile("mbarrier.inval.shared.b64 [%0];" :: "r"(su32(&s_mbar[1])) : "memory");
    }
    if (wid == 0)
        asm volatile("tcgen05.dealloc.cta_group::1.sync.aligned.b32 %0, %1;"
                     :: "r"(tmem), "r"(128u));
#else
    // ==================== SIMT fallback (sm_103 / host pass) ===============
    const int Z = gridDim.z;
    const int kcr = (g.K + Z - 1) / Z;
    int k0 = blockIdx.z * kcr;
    int k1 = k0 + kcr; if (k1 > g.K) k1 = g.K;

    __shared__ float As[16][72];
    __shared__ float Bs[16][136];

    const int rg = tid >> 4;    // 8 row groups x 8 rows
    const int cg = tid & 15;    // 16 col groups x 8 cols
    const bool fin = (gridDim.z == 1);
    float* Cz = g.C + (size_t)blockIdx.z * g.M * g.N;

    for (int mh = 0; mh < 128; mh += 64) {
        if (m0 + mh >= g.M) break;
        float acc[8][8];
#pragma unroll
        for (int i = 0; i < 8; i++)
#pragma unroll
            for (int j = 0; j < 8; j++) acc[i][j] = 0.f;

        for (int kt = k0; kt < k1; kt += 16) {
            for (int e = tid; e < 64 * 16; e += 128) {
                int rr = e >> 4, kk = e & 15;
                int gr = m0 + mh + rr, gk = kt + kk;
                As[kk][rr] = (gr < g.M && gk < k1) ? g.A[(size_t)gr * g.lda + gk] : 0.f;
            }
            for (int e = tid; e < 128 * 16; e += 128) {
                int cc = e >> 4, kk = e & 15;
                int gc = n0 + cc, gk = kt + kk;
                float w = 0.f;
                if (gc < g.N && gk < k1) {
                    const __nv_bfloat16* p = g.Wb + (size_t)gc * 3 * g.Kp;
                    w = __bfloat162float(p[gk]) + __bfloat162float(p[g.Kp + gk])
                      + __bfloat162float(p[2 * g.Kp + gk]);
                }
                Bs[kk][cc] = w;
            }
            __syncthreads();
#pragma unroll
            for (int kk = 0; kk < 16; kk++) {
                float a[8], b[8];
#pragma unroll
                for (int i = 0; i < 8; i++) a[i] = As[kk][rg * 8 + i];
#pragma unroll
                for (int j = 0; j < 8; j++) b[j] = Bs[kk][cg * 8 + j];
#pragma unroll
                for (int i = 0; i < 8; i++)
#pragma unroll
                    for (int j = 0; j < 8; j++) acc[i][j] += a[i] * b[j];
            }
            __syncthreads();
        }

#pragma unroll
        for (int i = 0; i < 8; i++) {
            int r = m0 + mh + rg * 8 + i;
            if (r >= g.M) continue;
#pragma unroll
            for (int j = 0; j < 8; j++) {
                int c = n0 + cg * 8 + j;
                if (c >= g.N) continue;
                float v = acc[i][j];
                if (fin && g.bias) v += g.bias[c];
                Cz[(size_t)r * g.N + c] = v;
            }
        }
    }
#endif
}

// ---------------- elementwise kernels ----------------
__global__ void finalize_k(const float* __restrict__ parts, int nz,
                           const float* __restrict__ bias,
                           float* __restrict__ out, int MN, int N, int act)
{
    int i = blockIdx.x * blockDim.x + threadIdx.x;
    if (i >= MN) return;
    float v = 0.f;
    for (int z = 0; z < nz; z++) v += parts[(size_t)z * MN + i];
    if (bias) v += bias[i % N];
    if (act) v = tanhf(v);
    out[i] = v;
}

__global__ void finalize_max_k(const float* __restrict__ pm, int nz,
                               const float* __restrict__ bias,
                               float* __restrict__ tm)
{
    int i = blockIdx.x * blockDim.x + threadIdx.x;
    if (i >= BB * MXO) return;
    int b = i / MXO, o = i % MXO;
    float v0 = bias[2 * o], v1 = bias[2 * o + 1];
    for (int z = 0; z < nz; z++) {
        const float* p = pm + ((size_t)z * BB + b) * MX2;
        v0 += p[2 * o]; v1 += p[2 * o + 1];
    }
    tm[i] = fmaxf(v0, v1);
}

__global__ void gru_gate_k(const float* __restrict__ gx, int zx, const float* __restrict__ bx,
                           const float* __restrict__ gh, int zh, const float* __restrict__ bh,
                           float* __restrict__ h, float* __restrict__ eout, int estride)
{
    int i = blockIdx.x * blockDim.x + threadIdx.x;
    if (i >= BB * HIDN) return;
    int b = i / HIDN, j = i % HIDN;
    float xr = 0.f, xz = 0.f, xn = 0.f, hr = 0.f, hz = 0.f, hn = 0.f;
    for (int z = 0; z < zx; z++) {
        const float* p = gx + ((size_t)z * BB + b) * G3;
        xr += p[j]; xz += p[HIDN + j]; xn += p[2 * HIDN + j];
    }
    if (bx) { xr += bx[j]; xz += bx[HIDN + j]; xn += bx[2 * HIDN + j]; }
    for (int z = 0; z < zh; z++) {
        const float* p = gh + ((size_t)z * BB + b) * G3;
        hr += p[j]; hz += p[HIDN + j]; hn += p[2 * HIDN + j];
    }
    hr += bh[j]; hz += bh[HIDN + j]; hn += bh[2 * HIDN + j];
    float r  = 1.f / (1.f + expf(-(xr + hr)));
    float zz = 1.f / (1.f + expf(-(xz + hz)));
    float n  = tanhf(xn + r * hn);
    float h2 = (1.f - zz) * n + zz * h[i];
    h[i] = h2;
    if (eout) eout[(size_t)b * estride + j] = h2;
}

__global__ void gru_gate2_k(const float* __restrict__ gxf, const float* __restrict__ gxb,
                            const float* __restrict__ pf, const float* __restrict__ pb,
                            int nz,
                            const float* __restrict__ bhf, const float* __restrict__ bhb,
                            float* __restrict__ hf, float* __restrict__ hb,
                            float* __restrict__ ef, float* __restrict__ eb)
{
    int i = blockIdx.x * blockDim.x + threadIdx.x;
    if (i >= 2 * BB * HIDN) return;
    int dir = (i >= BB * HIDN);
    int ii = dir ? i - BB * HIDN : i;
    int b = ii / HIDN, j = ii % HIDN;
    const float* gx = dir ? gxb : gxf;
    const float* phh = dir ? pb : pf;
    const float* bh = dir ? bhb : bhf;
    float* h  = dir ? hb : hf;
    float* eo = dir ? eb : ef;

    const float* q = gx + (size_t)b * G3;
    float xr = q[j], xz = q[HIDN + j], xn = q[2 * HIDN + j];
    float hr = bh[j], hz = bh[HIDN + j], hn = bh[2 * HIDN + j];
    for (int z = 0; z < nz; z++) {
        const float* p = phh + ((size_t)z * BB + b) * G3;
        hr += p[j]; hz += p[HIDN + j]; hn += p[2 * HIDN + j];
    }
    float r  = 1.f / (1.f + expf(-(xr + hr)));
    float zz = 1.f / (1.f + expf(-(xz + hz)));
    float n  = tanhf(xn + r * hn);
    float h2 = (1.f - zz) * n + zz * h[ii];
    h[ii] = h2;
    eo[(size_t)b * E2 + j] = h2;
}

__global__ void embed_k(const float* __restrict__ table, const int* __restrict__ idx,
                        float* __restrict__ out, int rows, int E)
{
    int i = blockIdx.x * blockDim.x + threadIdx.x;
    if (i >= rows * E) return;
    int r = i / E, e = i % E;
    out[i] = table[(size_t)idx[r] * E + e];
}

__global__ void copy_inp_k(const int* __restrict__ trg, int* __restrict__ inp)
{
    inp[threadIdx.x] = trg[threadIdx.x];
}

__global__ void attention_k(const float* __restrict__ pa,
                            const float* __restrict__ ep,
                            const float* __restrict__ ab,
                            const float* __restrict__ av,
                            const float* __restrict__ enc,
                            const float* __restrict__ demb,
                            const int*   __restrict__ inp,
                            float* __restrict__ x,
                            float* __restrict__ mi)
{
    const int b = blockIdx.x;
    const int tid = threadIdx.x;
    __shared__ float hqs[ATTD];
    __shared__ float al[S_LEN];
    __shared__ float red[8];

    for (int a = tid; a < ATTD; a += 256) {
        float s = 0.f;
#pragma unroll
        for (int z = 0; z < 8; z++) s += pa[((size_t)z * BB + b) * ATTD + a];
        hqs[a] = s;
    }
    __syncthreads();

    for (int s = 0; s < S_LEN; s++) {
        const float* eprow = ep + ((size_t)s * BB + b) * ATTD;
        float e = 0.f;
        for (int a = tid; a < ATTD; a += 256)
            e += av[a] * tanhf(hqs[a] + eprow[a] + ab[a]);
#pragma unroll
        for (int o = 16; o; o >>= 1) e += __shfl_down_sync(0xffffffffu, e, o);
        if ((tid & 31) == 0) red[tid >> 5] = e;
        __syncthreads();
        if (tid == 0) {
            float t = 0.f;
            for (int w = 0; w < 8; w++) t += red[w];
            al[s] = t;
        }
        __syncthreads();
    }

    if (tid == 0) {
        float m = -1e30f;
        for (int s = 0; s < S_LEN; s++) m = fmaxf(m, al[s]);
        float sum = 0.f;
        for (int s = 0; s < S_LEN; s++) { float e = expf(al[s] - m); al[s] = e; sum += e; }
        float inv = 1.f / sum;
        for (int s = 0; s < S_LEN; s++) al[s] *= inv;
    }
    __syncthreads();

    for (int hc = tid; hc < E2; hc += 256) {
        float c = 0.f;
        for (int s = 0; s < S_LEN; s++)
            c += al[s] * enc[((size_t)s * BB + b) * E2 + hc];
        x [(size_t)b * DXK + EMBD + hc] = c;
        mi[(size_t)b * MXK + HIDN + hc] = c;
    }
    const int tok = inp[b];
    for (int e = tid; e < EMBD; e += 256) {
        float vv = demb[(size_t)tok * EMBD + e];
        x [(size_t)b * DXK + e] = vv;
        mi[(size_t)b * MXK + G3 + e] = vv;
    }
}

__global__ void argmax_k(const float* __restrict__ pred, int* __restrict__ inp)
{
    __shared__ float sv[256];
    __shared__ int   si[256];
    int b = blockIdx.x;
    const float* row = pred + (size_t)b * OUTV;
    float best = -1e30f; int bi = 0;
    for (int i = threadIdx.x; i < OUTV; i += 256) {
        float v = row[i];
        if (v > best) { best = v; bi = i; }
    }
    sv[threadIdx.x] = best; si[threadIdx.x] = bi;
    __syncthreads();
    for (int s = 128; s; s >>= 1) {
        if (threadIdx.x < s) {
            float ov = sv[threadIdx.x + s]; int oi = si[threadIdx.x + s];
            if (ov > sv[threadIdx.x] || (ov == sv[threadIdx.x] && oi < si[threadIdx.x])) {
                sv[threadIdx.x] = ov; si[threadIdx.x] = oi;
            }
        }
        __syncthreads();
    }
    if (threadIdx.x == 0) inp[b] = si[0];
}

// ---------------- host helpers ----------------
static inline int up(int n, int b) { return (n + b - 1) / b; }

static inline TG mkt(const float* A, int lda, int K, int Kp,
                     const __nv_bfloat16* Wb, const float* bias, float* C,
                     int M, int N, int split)
{
    TG g;
    g.A = A; g.lda = lda; g.K = K; g.Kp = Kp;
    g.Wb = Wb; g.bias = bias; g.C = C; g.M = M; g.N = N;
    int K6 = 6 * Kp;
    g.kc = ((K6 + split - 1) / split + 63) & ~63;
    return g;
}

static inline void tg1(const TG& g, int split)
{
    dim3 grid(up(g.N, 128), up(g.M, 128), split);
    tgemm_k<<<grid, 128, TG_SMEM>>>(g, g, 0);
}

static inline void tg2(const TG& a, const TG& b, int split)
{
    dim3 grid(up(a.N, 128), 2, split);
    tgemm_k<<<grid, 128, TG_SMEM>>>(a, b, 1);
}

static inline void wconv(const float* W, int rs, int co,
                         __nv_bfloat16* Wb, int N, int K, int Kp)
{
    wconv_k<<<up(N * Kp, 256), 256>>>(W, rs, co, Wb, N, K, Kp);
}

extern "C" void kernel_launch(void* const* d_in, const int* in_sizes, int n_in,
                              void* d_out, int out_size)
{
    (void)in_sizes; (void)n_in; (void)out_size;
    const int*   src      = (const int*)  d_in[0];
    const int*   trg      = (const int*)  d_in[1];
    const float* enc_emb  = (const float*)d_in[2];
    const float* enc_wx_f = (const float*)d_in[3];
    const float* enc_wh_f = (const float*)d_in[4];
    const float* enc_bx_f = (const float*)d_in[5];
    const float* enc_bh_f = (const float*)d_in[6];
    const float* enc_wx_b = (const float*)d_in[7];
    const float* enc_wh_b = (const float*)d_in[8];
    const float* enc_bx_b = (const float*)d_in[9];
    const float* enc_bh_b = (const float*)d_in[10];
    const float* enc_fc_w = (const float*)d_in[11];
    const float* enc_fc_b = (const float*)d_in[12];
    const float* attn_w   = (const float*)d_in[13];
    const float* attn_b   = (const float*)d_in[14];
    const float* attn_v   = (const float*)d_in[15];
    const float* dec_emb  = (const float*)d_in[16];
    const float* dec_wx   = (const float*)d_in[17];
    const float* dec_wh   = (const float*)d_in[18];
    const float* dec_bx   = (const float*)d_in[19];
    const float* dec_bh   = (const float*)d_in[20];
    const float* max_w    = (const float*)d_in[21];
    const float* max_b    = (const float*)d_in[22];
    const float* out_w    = (const float*)d_in[23];
    const float* out_b    = (const float*)d_in[24];

    cudaFuncSetAttribute(tgemm_k, cudaFuncAttributeMaxDynamicSharedMemorySize, TG_SMEM);

    float* ws = nullptr; int* inp = nullptr; __nv_bfloat16* wb = nullptr;
    cudaGetSymbolAddress((void**)&ws, g_ws);
    cudaGetSymbolAddress((void**)&inp, g_inp);
    cudaGetSymbolAddress((void**)&wb, g_wb);

    float* emb = ws + O_EMB;
    float* gxf = ws + O_GXF;
    float* gxb = ws + O_GXB;
    float* enc = ws + O_ENC;
    float* ep  = ws + O_EP;
    float* pa  = ws + O_PA;
    float* pb  = ws + O_PB;
    float* pm  = ws + O_PM;
    float* hf  = ws + O_HF;
    float* hb  = ws + O_HB;
    float* hd  = ws + O_HD;
    float* x   = ws + O_X;
    float* mi  = ws + O_MI;
    float* tm  = ws + O_TM;
    float* out = (float*)d_out;

    // ---- weight split conversion ----
    wconv(enc_wx_f, EMBD, 0,    wb + WB_EXF, 3000, EMBD, KP_EX);
    wconv(enc_wx_b, EMBD, 0,    wb + WB_EXB, 3000, EMBD, KP_EX);
    wconv(enc_wh_f, HIDN, 0,    wb + WB_WHF, 3000, HIDN, KP_WH);
    wconv(enc_wh_b, HIDN, 0,    wb + WB_WHB, 3000, HIDN, KP_WH);
    wconv(enc_fc_w, HIDN, 0,    wb + WB_FC,  1000, HIDN, KP_WH);
    wconv(attn_w,   G3,   0,    wb + WB_AWH, 1000, HIDN, KP_WH);
    wconv(attn_w,   G3,   HIDN, wb + WB_AWE, 1000, E2,   KP_AWE);
    wconv(dec_wx,   DXK,  0,    wb + WB_DWX, 3000, DXK,  KP_DWX);
    wconv(dec_wh,   HIDN, 0,    wb + WB_DWH, 3000, HIDN, KP_WH);
    wconv(max_w,    MXK,  0,    wb + WB_MXW, 1000, MXK,  KP_MXW);
    wconv(out_w,    MXO,  0,    wb + WB_OUW, 30000, MXO, KP_OUW);

    cudaMemsetAsync(out, 0, (size_t)BB * OUTV * sizeof(float));

    // ---------------- Encoder ----------------
    embed_k<<<up(S_LEN * BB * EMBD, 256), 256>>>(enc_emb, src, emb, S_LEN * BB, EMBD);
    tg1(mkt(emb, EMBD, EMBD, KP_EX, wb + WB_EXF, enc_bx_f, gxf, S_LEN * BB, G3, 1), 1);
    tg1(mkt(emb, EMBD, EMBD, KP_EX, wb + WB_EXB, enc_bx_b, gxb, S_LEN * BB, G3, 1), 1);

    cudaMemsetAsync(hf, 0, (size_t)BB * HIDN * sizeof(float));
    cudaMemsetAsync(hb, 0, (size_t)BB * HIDN * sizeof(float));

    for (int s = 0; s < S_LEN; s++) {
        int sb = S_LEN - 1 - s;
        TG gf = mkt(hf, HIDN, HIDN, KP_WH, wb + WB_WHF, nullptr, pa, BB, G3, 4);
        TG gb = mkt(hb, HIDN, HIDN, KP_WH, wb + WB_WHB, nullptr, pb, BB, G3, 4);
        tg2(gf, gb, 4);
        gru_gate2_k<<<up(2 * BB * HIDN, 256), 256>>>(
            gxf + (size_t)s * BB * G3, gxb + (size_t)sb * BB * G3,
            pa, pb, 4, enc_bh_f, enc_bh_b, hf, hb,
            enc + (size_t)s * BB * E2, enc + (size_t)sb * BB * E2 + HIDN);
    }

    tg1(mkt(hb, HIDN, HIDN, KP_WH, wb + WB_FC, nullptr, pa, BB, HIDN, 8), 8);
    finalize_k<<<up(BB * HIDN, 256), 256>>>(pa, 8, enc_fc_b, hd, BB * HIDN, HIDN, 1);
    tg1(mkt(enc, E2, E2, KP_AWE, wb + WB_AWE, nullptr, ep, S_LEN * BB, ATTD, 1), 1);

    // ---------------- Decoder ----------------
    copy_inp_k<<<1, BB>>>(trg, inp);
    for (int t = 0; t < T_LEN - 1; t++) {
        tg1(mkt(hd, HIDN, HIDN, KP_WH, wb + WB_AWH, nullptr, pa, BB, ATTD, 8), 8);
        attention_k<<<BB, 256>>>(pa, ep, attn_b, attn_v, enc, dec_emb, inp, x, mi);
        TG ga = mkt(x,  DXK,  DXK,  KP_DWX, wb + WB_DWX, nullptr, pa, BB, G3, 4);
        TG gh = mkt(hd, HIDN, HIDN, KP_WH,  wb + WB_DWH, nullptr, pb, BB, G3, 4);
        tg2(ga, gh, 4);
        gru_gate_k<<<up(BB * HIDN, 256), 256>>>(pa, 4, dec_bx, pb, 4, dec_bh, hd, mi, MXK);
        tg1(mkt(mi, MXK, MXK, KP_MXW, wb + WB_MXW, nullptr, pm, BB, MX2, 8), 8);
        finalize_max_k<<<up(BB * MXO, 256), 256>>>(pm, 8, max_b, tm);
        float* pred = out + (size_t)(t + 1) * BB * OUTV;
        tg1(mkt(tm, MXO, MXO, KP_OUW, wb + WB_OUW, out_b, pred, BB, OUTV, 1), 1);
        argmax_k<<<BB, 256>>>(pred, inp);
    }
}

// round 7
// speedup vs baseline: 3.5486x; 3.5486x over previous
#include <cuda_runtime.h>
#include <cuda_bf16.h>
#include <math.h>
#include <stdint.h>

#define S_LEN 40
#define T_LEN 30
#define BB    64
#define EMBD  620
#define HIDN  1000
#define ATTD  1000
#define MXO   500
#define OUTV  30000
#define G3    3000
#define E2    2000
#define DXK   2620
#define MXK   3620
#define MX2   1000

// padded K (multiple of 64) per operand family
#define KP_EX  640     // K=620  (emb)
#define KP_WH  1024    // K=1000 (h)
#define KP_EN  2048    // K=2000 (enc_out)
#define KP_X   2624    // K=2620 (x)
#define KP_MI  3648    // K=3620 (mi)
#define KP_TM  512     // K=500  (tm)

// ---------------- fp32 workspace ----------------
static const size_t O_GXF = 0;
static const size_t O_GXB = O_GXF + (size_t)S_LEN*BB*G3;
static const size_t O_ENC = O_GXB + (size_t)S_LEN*BB*G3;
static const size_t O_EP  = O_ENC + (size_t)S_LEN*BB*E2;
static const size_t O_PA  = O_EP  + (size_t)S_LEN*BB*ATTD;
static const size_t O_PB  = O_PA  + (size_t)8*BB*G3;
static const size_t O_PM  = O_PB  + (size_t)8*BB*G3;
static const size_t O_HF  = O_PM  + (size_t)8*BB*MX2;
static const size_t O_HB  = O_HF  + (size_t)BB*HIDN;
static const size_t O_HD  = O_HB  + (size_t)BB*HIDN;
static const size_t ARENA = O_HD  + (size_t)BB*HIDN;

__device__ __align__(256) float g_ws[ARENA];
__device__ int g_inp[BB];

// ---------------- bf16 split weight arena: W[N,K] -> [N,3*Kp] = [h|m|l] ----
static const size_t WB_EXF = 0;
static const size_t WB_EXB = WB_EXF + (size_t)3000*3*KP_EX;
static const size_t WB_WHF = WB_EXB + (size_t)3000*3*KP_EX;
static const size_t WB_WHB = WB_WHF + (size_t)3000*3*KP_WH;
static const size_t WB_FC  = WB_WHB + (size_t)3000*3*KP_WH;
static const size_t WB_AWH = WB_FC  + (size_t)1000*3*KP_WH;
static const size_t WB_AWE = WB_AWH + (size_t)1000*3*KP_WH;
static const size_t WB_DWX = WB_AWE + (size_t)1000*3*KP_EN;
static const size_t WB_DWH = WB_DWX + (size_t)3000*3*KP_X;
static const size_t WB_MXW = WB_DWH + (size_t)3000*3*KP_WH;
static const size_t WB_OUW = WB_MXW + (size_t)1000*3*KP_MI;
static const size_t WB_TOT = WB_OUW + (size_t)30000*3*KP_TM;

__device__ __align__(256) __nv_bfloat16 g_wb[WB_TOT];

// ---------------- bf16 split activation arenas (pads stay zero) ----------
static const size_t AB_EMB = 0;                                   // [S*B,3*KP_EX]
static const size_t AB_ENC = AB_EMB + (size_t)S_LEN*BB*3*KP_EX;   // [S*B,3*KP_EN]
static const size_t AB_HF  = AB_ENC + (size_t)S_LEN*BB*3*KP_EN;   // [B,3*KP_WH]
static const size_t AB_HB  = AB_HF  + (size_t)BB*3*KP_WH;
static const size_t AB_HD  = AB_HB  + (size_t)BB*3*KP_WH;
static const size_t AB_X   = AB_HD  + (size_t)BB*3*KP_WH;         // [B,3*KP_X]
static const size_t AB_MI  = AB_X   + (size_t)BB*3*KP_X;          // [B,3*KP_MI]
static const size_t AB_TM  = AB_MI  + (size_t)BB*3*KP_MI;         // [B,3*KP_TM]
static const size_t AB_TOT = AB_TM  + (size_t)BB*3*KP_TM;

__device__ __align__(256) __nv_bfloat16 g_ab[AB_TOT];

// ---------------- helpers ----------------
__device__ __forceinline__ uint32_t su32(const void* p)
{
    uint32_t a;
    asm("{ .reg .u64 t; cvta.to.shared.u64 t, %1; cvt.u32.u64 %0, t; }"
        : "=r"(a) : "l"(p));
    return a;
}
__device__ __forceinline__ uint64_t mkdesc(uint32_t addr)
{
    const uint64_t base = (uint64_t(2) << 61) | (uint64_t(1) << 46) |
                          (uint64_t(64) << 32) | (uint64_t(1) << 16);
    return base | ((uint64_t)(addr >> 4) & 0x3FFF);
}
__device__ __forceinline__ void mbar_init(uint32_t mb, uint32_t cnt)
{
    asm volatile("mbarrier.init.shared.b64 [%0], %1;" :: "r"(mb), "r"(cnt) : "memory");
}
__device__ __forceinline__ void mbar_wait(uint32_t mb, int parity)
{
    asm volatile(
        "{\n\t.reg .pred P;\n\t"
        "WL_%=:\n\t"
        "mbarrier.try_wait.parity.acquire.cta.shared::cta.b64 P, [%0], %1, 0x989680;\n\t"
        "@P bra.uni WD_%=;\n\t"
        "bra.uni WL_%=;\n\t"
        "WD_%=:\n\t}"
        :: "r"(mb), "r"(parity) : "memory");
}
__device__ __forceinline__ void mma_bf16_ss(uint32_t d, uint64_t ad, uint64_t bd,
                                            uint32_t idesc, uint32_t acc)
{
    asm volatile(
        "{\n\t.reg .pred p;\n\t"
        "setp.ne.u32 p, %5, 0;\n\t"
        "tcgen05.mma.cta_group::1.kind::f16 [%0], %1, %2, %3, {%4,%4,%4,%4}, p;\n\t}"
        :: "r"(d), "l"(ad), "l"(bd), "r"(idesc), "r"(0u), "r"(acc) : "memory");
}
__device__ __forceinline__ void tc_commit(uint32_t mb)
{
    asm volatile(
        "tcgen05.commit.cta_group::1.mbarrier::arrive::one.shared::cluster.b64 [%0];"
        :: "r"(mb) : "memory");
}
#define LDTM_X32(r, ta) \
    asm volatile( \
        "tcgen05.ld.sync.aligned.32x32b.x32.b32 " \
        "{%0,%1,%2,%3,%4,%5,%6,%7,%8,%9,%10,%11,%12,%13,%14,%15," \
        "%16,%17,%18,%19,%20,%21,%22,%23,%24,%25,%26,%27,%28,%29,%30,%31}, [%32];" \
        : "=r"((r)[0]),"=r"((r)[1]),"=r"((r)[2]),"=r"((r)[3]), \
          "=r"((r)[4]),"=r"((r)[5]),"=r"((r)[6]),"=r"((r)[7]), \
          "=r"((r)[8]),"=r"((r)[9]),"=r"((r)[10]),"=r"((r)[11]), \
          "=r"((r)[12]),"=r"((r)[13]),"=r"((r)[14]),"=r"((r)[15]), \
          "=r"((r)[16]),"=r"((r)[17]),"=r"((r)[18]),"=r"((r)[19]), \
          "=r"((r)[20]),"=r"((r)[21]),"=r"((r)[22]),"=r"((r)[23]), \
          "=r"((r)[24]),"=r"((r)[25]),"=r"((r)[26]),"=r"((r)[27]), \
          "=r"((r)[28]),"=r"((r)[29]),"=r"((r)[30]),"=r"((r)[31]) \
        : "r"(ta))

// idesc: F32 accum, BF16 A/B K-major, M=128, N=128
#define TG_IDESC 0x8200490u
#define TG_SMEM  (1024 + 2*3*16384*2)   // slack + double-buffered 3A+3B tiles

// 3-way bf16 split: h = rn(a), m = rn(a-h), l = rn(a-h-m)
__device__ __forceinline__ void wsplit3(__nv_bfloat16* row, int Kp, int k, float a)
{
    __nv_bfloat16 h = __float2bfloat16(a);
    float r1 = a - __bfloat162float(h);
    __nv_bfloat16 m = __float2bfloat16(r1);
    float r2 = r1 - __bfloat162float(m);
    row[k] = h; row[Kp + k] = m; row[2 * Kp + k] = __float2bfloat16(r2);
}

// ---------------- weight conversion ----------------
__global__ void wconv_k(const float* __restrict__ W, int rs, int co,
                        __nv_bfloat16* __restrict__ Wb, int N, int K, int Kp)
{
    int i = blockIdx.x * blockDim.x + threadIdx.x;
    if (i >= N * Kp) return;
    int n = i / Kp, k = i - n * Kp;
    float a = (k < K) ? W[(size_t)n * rs + co + k] : 0.f;
    wsplit3(Wb + (size_t)n * 3 * Kp, Kp, k, a);
}

// ---------------------------------------------------------------------------
// tcgen05 GEMM: C[M,N] = sum over 6 bf16 segments of Ab[M,3Kp] @ Wb[N,3Kp]^T
// Window-ordered: per 64-col window stage 3 A-parts + 3 B-parts once, issue
// 6 segment MMAs. grid.z split over windows (kcw windows per chunk).
// partial z -> C + z*M*N; bias only when gridDim.z==1.
// dual=1: blockIdx.y picks arg set (M<=128); else blockIdx.y = M tile (128).
// ---------------------------------------------------------------------------
struct TG {
    const __nv_bfloat16* Ab;
    const __nv_bfloat16* Wb;
    const float* bias;
    float* C;
    int M, N, Kp, kcw;
};

__global__ void __launch_bounds__(256) tgemm_k(TG g0, TG g1, int dual)
{
    const TG g = (dual && blockIdx.y) ? g1 : g0;
    const int m0 = dual ? 0 : blockIdx.y * 128;
    const int n0 = blockIdx.x * 128;
    const int tid = threadIdx.x;
    const int Kp = g.Kp;

#if defined(__CUDA_ARCH_FEAT_SM103_ALL)
    const int Wn = Kp >> 6;
    int w0 = blockIdx.z * g.kcw;
    int w1 = w0 + g.kcw; if (w1 > Wn) w1 = Wn;
    const int nw = (w1 > w0) ? (w1 - w0) : 0;

    const int wid = tid >> 5;
    const int lane = tid & 31;

    extern __shared__ __align__(16) char dyn[];
    uint32_t dbase = (su32(dyn) + 1023u) & ~1023u;
    // buf layout: A tiles [buf][p] then B tiles [buf][p], 16KB each
    #define SA(buf, p) (dbase + ((buf) * 3 + (p)) * 16384u)
    #define SB(buf, p) (dbase + 98304u + ((buf) * 3 + (p)) * 16384u)

    __shared__ __align__(8) unsigned long long s_mbar[2];
    __shared__ uint32_t s_tptr;

    if (wid == 0) {
        asm volatile("tcgen05.alloc.cta_group::1.sync.aligned.shared::cta.b32 [%0], %1;"
                     :: "r"(su32(&s_tptr)), "r"(128u) : "memory");
        asm volatile("tcgen05.relinquish_alloc_permit.cta_group::1.sync.aligned;");
    }
    if (tid == 0) { mbar_init(su32(&s_mbar[0]), 1); mbar_init(su32(&s_mbar[1]), 1); }
    __syncthreads();
    const uint32_t tmem = s_tptr;

    // staging coordinates: thread t handles row r = t>>1, 32-col half c
    const int srow = tid >> 1;
    const int scol = (tid & 1) * 32;           // bf16 elements
    const int am = m0 + srow;
    const int bn = n0 + srow;
    const bool av = am < g.M;
    const bool bv = bn < g.N;
    const __nv_bfloat16* Arow = g.Ab + (size_t)am * 3 * Kp + scol;
    const __nv_bfloat16* Brow = g.Wb + (size_t)bn * 3 * Kp + scol;

    int ph0 = 0, ph1 = 0;
    const int segA[6] = {0, 1, 2, 0, 1, 0};
    const int segB[6] = {0, 0, 0, 1, 1, 2};

    for (int i = 0; i < nw; i++) {
        const int buf = i & 1;
        const int w = w0 + i;
        const int kb = w * 64;

        if (i >= 2) {
            if (buf == 0) { mbar_wait(su32(&s_mbar[0]), ph0); ph0 ^= 1; }
            else          { mbar_wait(su32(&s_mbar[1]), ph1); ph1 ^= 1; }
        }

        // stage 3 A parts + 3 B parts (pure copies)
#pragma unroll
        for (int p = 0; p < 3; p++) {
            const __nv_bfloat16* Ap = Arow + (size_t)p * Kp + kb;
            const __nv_bfloat16* Bp = Brow + (size_t)p * Kp + kb;
#pragma unroll
            for (int j = 0; j < 4; j++) {
                uint4 ta = make_uint4(0,0,0,0), tb = make_uint4(0,0,0,0);
                if (av) ta = *(const uint4*)(Ap + j * 8);
                if (bv) tb = *(const uint4*)(Bp + j * 8);
                uint32_t off = srow * 128 + scol * 2 + j * 16;
                uint32_t sw = off ^ ((off >> 3) & 0x70);
                asm volatile("st.shared.v4.b32 [%0], {%1,%2,%3,%4};"
                             :: "r"(SA(buf,p) + sw), "r"(ta.x), "r"(ta.y), "r"(ta.z), "r"(ta.w) : "memory");
                asm volatile("st.shared.v4.b32 [%0], {%1,%2,%3,%4};"
                             :: "r"(SB(buf,p) + sw), "r"(tb.x), "r"(tb.y), "r"(tb.z), "r"(tb.w) : "memory");
            }
        }
        asm volatile("fence.proxy.async.shared::cta;" ::: "memory");
        __syncthreads();

        if (tid == 0) {
            asm volatile("tcgen05.fence::after_thread_sync;" ::: "memory");
#pragma unroll
            for (int s = 0; s < 6; s++) {
                uint64_t ad = mkdesc(SA(buf, segA[s]));
                uint64_t bd = mkdesc(SB(buf, segB[s]));
#pragma unroll
                for (int q = 0; q < 4; q++)
                    mma_bf16_ss(tmem, ad + 2 * q, bd + 2 * q, TG_IDESC,
                                (i == 0 && s == 0 && q == 0) ? 0u : 1u);
            }
            tc_commit(su32(&s_mbar[buf]));
        }
    }

    for (int t = (nw >= 2 ? nw - 2 : 0); t < nw; t++) {
        if ((t & 1) == 0) { mbar_wait(su32(&s_mbar[0]), ph0); ph0 ^= 1; }
        else              { mbar_wait(su32(&s_mbar[1]), ph1); ph1 ^= 1; }
    }
    asm volatile("tcgen05.fence::after_thread_sync;" ::: "memory");

    const bool fin = (gridDim.z == 1);
    float* Cz = g.C + (size_t)blockIdx.z * g.M * g.N;

    if (wid < 4) {
        const int r = m0 + wid * 32 + lane;
        if (nw == 0) {
            if (r < g.M)
                for (int j = 0; j < 128; j++) {
                    int c = n0 + j;
                    if (c < g.N) Cz[(size_t)r * g.N + c] = (fin && g.bias) ? g.bias[c] : 0.f;
                }
        } else {
#pragma unroll
            for (int base = 0; base < 128; base += 32) {
                uint32_t regs[32];
                LDTM_X32(regs, tmem + base);
                asm volatile("tcgen05.wait::ld.sync.aligned;" ::: "memory");
                if (r < g.M) {
#pragma unroll
                    for (int j = 0; j < 32; j++) {
                        int c = n0 + base + j;
                        if (c < g.N) {
                            float v = __uint_as_float(regs[j]);
                            if (fin && g.bias) v += g.bias[c];
                            Cz[(size_t)r * g.N + c] = v;
                        }
                    }
                }
            }
        }
    }

    __syncthreads();
    if (tid == 0) {
        asm volatile("mbarrier.inval.shared.b64 [%0];" :: "r"(su32(&s_mbar[0])) : "memory");
        asm volatile("mbarrier.inval.shared.b64 [%0];" :: "r"(su32(&s_mbar[1])) : "memory");
    }
    if (wid == 0)
        asm volatile("tcgen05.dealloc.cta_group::1.sync.aligned.b32 %0, %1;"
                     :: "r"(tmem), "r"(128u));
    #undef SA
    #undef SB
#else
    // ---------------- SIMT fallback (sm_103 / host pass) ----------------
    const int kcr = g.kcw * 64;
    int k0 = blockIdx.z * kcr;
    int k1 = k0 + kcr; if (k1 > Kp) k1 = Kp;

    __shared__ float As[16][72];
    __shared__ float Bs[16][136];

    const int rg = (tid & 127) >> 4;
    const int cg = tid & 15;
    const bool half2 = tid >= 128;
    const bool fin = (gridDim.z == 1);
    float* Cz = g.C + (size_t)blockIdx.z * g.M * g.N;

    if (!half2) {
        for (int mh = 0; mh < 128; mh += 64) {
            if (m0 + mh >= g.M) break;
            float acc[8][8];
            for (int i = 0; i < 8; i++)
                for (int j = 0; j < 8; j++) acc[i][j] = 0.f;
            for (int kt = k0; kt < k1; kt += 16) {
                __syncthreads();
                for (int e = tid; e < 64 * 16; e += 128) {
                    int rr = e >> 4, kk = e & 15;
                    int gr = m0 + mh + rr, gk = kt + kk;
                    float w = 0.f;
                    if (gr < g.M && gk < k1) {
                        const __nv_bfloat16* p = g.Ab + (size_t)gr * 3 * Kp;
                        w = __bfloat162float(p[gk]) + __bfloat162float(p[Kp + gk])
                          + __bfloat162float(p[2 * Kp + gk]);
                    }
                    As[kk][rr] = w;
                }
                for (int e = tid; e < 128 * 16; e += 128) {
                    int cc = e >> 4, kk = e & 15;
                    int gc = n0 + cc, gk = kt + kk;
                    float w = 0.f;
                    if (gc < g.N && gk < k1) {
                        const __nv_bfloat16* p = g.Wb + (size_t)gc * 3 * Kp;
                        w = __bfloat162float(p[gk]) + __bfloat162float(p[Kp + gk])
                          + __bfloat162float(p[2 * Kp + gk]);
                    }
                    Bs[kk][cc] = w;
                }
                __syncthreads();
                for (int kk = 0; kk < 16; kk++) {
                    float a[8], b[8];
                    for (int i = 0; i < 8; i++) a[i] = As[kk][rg * 8 + i];
                    for (int j = 0; j < 8; j++) b[j] = Bs[kk][cg * 8 + j];
                    for (int i = 0; i < 8; i++)
                        for (int j = 0; j < 8; j++) acc[i][j] += a[i] * b[j];
                }
            }
            for (int i = 0; i < 8; i++) {
                int r = m0 + mh + rg * 8 + i;
                if (r >= g.M) continue;
                for (int j = 0; j < 8; j++) {
                    int c = n0 + cg * 8 + j;
                    if (c >= g.N) continue;
                    float v = acc[i][j];
                    if (fin && g.bias) v += g.bias[c];
                    Cz[(size_t)r * g.N + c] = v;
                }
            }
        }
    } else {
        for (int mh = 0; mh < 128; mh += 64) {
            if (m0 + mh >= g.M) break;
            for (int kt = k0; kt < k1; kt += 16) { __syncthreads(); __syncthreads(); }
        }
    }
#endif
}

// ---------------- elementwise kernels ----------------
__global__ void finalize_tanh_hd_k(const float* __restrict__ parts, int nz,
                                   const float* __restrict__ bias,
                                   float* __restrict__ hd,
                                   __nv_bfloat16* __restrict__ Ahd)
{
    int i = blockIdx.x * blockDim.x + threadIdx.x;
    if (i >= BB * HIDN) return;
    int b = i / HIDN, j = i % HIDN;
    float v = 0.f;
    for (int z = 0; z < nz; z++) v += parts[(size_t)z * BB * HIDN + i];
    v = tanhf(v + bias[j]);
    hd[i] = v;
    wsplit3(Ahd + (size_t)b * 3 * KP_WH, KP_WH, j, v);
}

__global__ void finalize_max_k(const float* __restrict__ pm, int nz,
                               const float* __restrict__ bias,
                               __nv_bfloat16* __restrict__ Atm)
{
    int i = blockIdx.x * blockDim.x + threadIdx.x;
    if (i >= BB * MXO) return;
    int b = i / MXO, o = i % MXO;
    float v0 = bias[2 * o], v1 = bias[2 * o + 1];
    for (int z = 0; z < nz; z++) {
        const float* p = pm + ((size_t)z * BB + b) * MX2;
        v0 += p[2 * o]; v1 += p[2 * o + 1];
    }
    wsplit3(Atm + (size_t)b * 3 * KP_TM, KP_TM, o, fmaxf(v0, v1));
}

// decoder GRU gate: updates hd fp32 + Ahd split + Ami[0:HIDN) split
__global__ void gru_gate_k(const float* __restrict__ gx, int zx, const float* __restrict__ bx,
                           const float* __restrict__ gh, int zh, const float* __restrict__ bh,
                           float* __restrict__ h,
                           __nv_bfloat16* __restrict__ Ahd,
                           __nv_bfloat16* __restrict__ Ami)
{
    int i = blockIdx.x * blockDim.x + threadIdx.x;
    if (i >= BB * HIDN) return;
    int b = i / HIDN, j = i % HIDN;
    float xr = 0.f, xz = 0.f, xn = 0.f, hr = 0.f, hz = 0.f, hn = 0.f;
    for (int z = 0; z < zx; z++) {
        const float* p = gx + ((size_t)z * BB + b) * G3;
        xr += p[j]; xz += p[HIDN + j]; xn += p[2 * HIDN + j];
    }
    xr += bx[j]; xz += bx[HIDN + j]; xn += bx[2 * HIDN + j];
    for (int z = 0; z < zh; z++) {
        const float* p = gh + ((size_t)z * BB + b) * G3;
        hr += p[j]; hz += p[HIDN + j]; hn += p[2 * HIDN + j];
    }
    hr += bh[j]; hz += bh[HIDN + j]; hn += bh[2 * HIDN + j];
    float r  = 1.f / (1.f + expf(-(xr + hr)));
    float zz = 1.f / (1.f + expf(-(xz + hz)));
    float n  = tanhf(xn + r * hn);
    float h2 = (1.f - zz) * n + zz * h[i];
    h[i] = h2;
    wsplit3(Ahd + (size_t)b * 3 * KP_WH, KP_WH, j, h2);
    wsplit3(Ami + (size_t)b * 3 * KP_MI, KP_MI, j, h2);
}

// paired encoder GRU gate: fwd + bwd; updates h fp32, Ah split, enc fp32,
// Aenc split. fwd timestep sf, bwd timestep sb.
__global__ void gru_gate2_k(const float* __restrict__ gxf, const float* __restrict__ gxb,
                            const float* __restrict__ pf, const float* __restrict__ pb,
                            int nz,
                            const float* __restrict__ bhf, const float* __restrict__ bhb,
                            float* __restrict__ hf, float* __restrict__ hb,
                            __nv_bfloat16* __restrict__ Ahf,
                            __nv_bfloat16* __restrict__ Ahb,
                            float* __restrict__ enc,
                            __nv_bfloat16* __restrict__ Aenc,
                            int sf, int sb)
{
    int i = blockIdx.x * blockDim.x + threadIdx.x;
    if (i >= 2 * BB * HIDN) return;
    int dir = (i >= BB * HIDN);
    int ii = dir ? i - BB * HIDN : i;
    int b = ii / HIDN, j = ii % HIDN;
    const float* gx = dir ? gxb : gxf;
    const float* phh = dir ? pb : pf;
    const float* bh = dir ? bhb : bhf;
    float* h = dir ? hb : hf;

    const float* q = gx + (size_t)b * G3;
    float xr = q[j], xz = q[HIDN + j], xn = q[2 * HIDN + j];
    float hr = bh[j], hz = bh[HIDN + j], hn = bh[2 * HIDN + j];
    for (int z = 0; z < nz; z++) {
        const float* p = phh + ((size_t)z * BB + b) * G3;
        hr += p[j]; hz += p[HIDN + j]; hn += p[2 * HIDN + j];
    }
    float r  = 1.f / (1.f + expf(-(xr + hr)));
    float zz = 1.f / (1.f + expf(-(xz + hz)));
    float n  = tanhf(xn + r * hn);
    float h2 = (1.f - zz) * n + zz * h[ii];
    h[ii] = h2;
    wsplit3((dir ? Ahb : Ahf) + (size_t)b * 3 * KP_WH, KP_WH, j, h2);
    int row = (dir ? sb : sf) * BB + b;
    int col = dir ? HIDN + j : j;
    enc[(size_t)row * E2 + col] = h2;
    wsplit3(Aenc + (size_t)row * 3 * KP_EN, KP_EN, col, h2);
}

__global__ void embed_split_k(const float* __restrict__ table, const int* __restrict__ idx,
                              __nv_bfloat16* __restrict__ Ab, int rows)
{
    int i = blockIdx.x * blockDim.x + threadIdx.x;
    if (i >= rows * EMBD) return;
    int r = i / EMBD, e = i % EMBD;
    wsplit3(Ab + (size_t)r * 3 * KP_EX, KP_EX, e, table[(size_t)idx[r] * EMBD + e]);
}

__global__ void copy_inp_k(const int* __restrict__ trg, int* __restrict__ inp)
{
    inp[threadIdx.x] = trg[threadIdx.x];
}

// fused attention: hq partial-sum + energy + softmax + context + dec-embed
// gather; writes split x (Ax) and split mi[HIDN:] (Ami).
__global__ void attention_k(const float* __restrict__ pa,
                            const float* __restrict__ ep,
                            const float* __restrict__ ab,
                            const float* __restrict__ av,
                            const float* __restrict__ enc,
                            const float* __restrict__ demb,
                            const int*   __restrict__ inp,
                            __nv_bfloat16* __restrict__ Ax,
                            __nv_bfloat16* __restrict__ Ami)
{
    const int b = blockIdx.x;
    const int tid = threadIdx.x;
    __shared__ float hqs[ATTD];
    __shared__ float al[S_LEN];
    __shared__ float red[8];

    for (int a = tid; a < ATTD; a += 256) {
        float s = 0.f;
#pragma unroll
        for (int z = 0; z < 8; z++) s += pa[((size_t)z * BB + b) * ATTD + a];
        hqs[a] = s;
    }
    __syncthreads();

    for (int s = 0; s < S_LEN; s++) {
        const float* eprow = ep + ((size_t)s * BB + b) * ATTD;
        float e = 0.f;
        for (int a = tid; a < ATTD; a += 256)
            e += av[a] * tanhf(hqs[a] + eprow[a] + ab[a]);
#pragma unroll
        for (int o = 16; o; o >>= 1) e += __shfl_down_sync(0xffffffffu, e, o);
        if ((tid & 31) == 0) red[tid >> 5] = e;
        __syncthreads();
        if (tid == 0) {
            float t = 0.f;
            for (int w = 0; w < 8; w++) t += red[w];
            al[s] = t;
        }
        __syncthreads();
    }

    if (tid == 0) {
        float m = -1e30f;
        for (int s = 0; s < S_LEN; s++) m = fmaxf(m, al[s]);
        float sum = 0.f;
        for (int s = 0; s < S_LEN; s++) { float e = expf(al[s] - m); al[s] = e; sum += e; }
        float inv = 1.f / sum;
        for (int s = 0; s < S_LEN; s++) al[s] *= inv;
    }
    __syncthreads();

    __nv_bfloat16* xrow = Ax + (size_t)b * 3 * KP_X;
    __nv_bfloat16* mrow = Ami + (size_t)b * 3 * KP_MI;
    for (int hc = tid; hc < E2; hc += 256) {
        float c = 0.f;
        for (int s = 0; s < S_LEN; s++)
            c += al[s] * enc[((size_t)s * BB + b) * E2 + hc];
        wsplit3(xrow, KP_X, EMBD + hc, c);
        wsplit3(mrow, KP_MI, HIDN + hc, c);
    }
    const int tok = inp[b];
    for (int e = tid; e < EMBD; e += 256) {
        float vv = demb[(size_t)tok * EMBD + e];
        wsplit3(xrow, KP_X, e, vv);
        wsplit3(mrow, KP_MI, G3 + e, vv);
    }
}

__global__ void argmax_k(const float* __restrict__ pred, int* __restrict__ inp)
{
    __shared__ float sv[256];
    __shared__ int   si[256];
    int b = blockIdx.x;
    const float* row = pred + (size_t)b * OUTV;
    float best = -1e30f; int bi = 0;
    for (int i = threadIdx.x; i < OUTV; i += 256) {
        float v = row[i];
        if (v > best) { best = v; bi = i; }
    }
    sv[threadIdx.x] = best; si[threadIdx.x] = bi;
    __syncthreads();
    for (int s = 128; s; s >>= 1) {
        if (threadIdx.x < s) {
            float ov = sv[threadIdx.x + s]; int oi = si[threadIdx.x + s];
            if (ov > sv[threadIdx.x] || (ov == sv[threadIdx.x] && oi < si[threadIdx.x])) {
                sv[threadIdx.x] = ov; si[threadIdx.x] = oi;
            }
        }
        __syncthreads();
    }
    if (threadIdx.x == 0) inp[b] = si[0];
}

// ---------------- host helpers ----------------
static inline int up(int n, int b) { return (n + b - 1) / b; }

static inline TG mkt(const __nv_bfloat16* Ab, const __nv_bfloat16* Wb,
                     const float* bias, float* C, int M, int N, int Kp, int split)
{
    TG g;
    g.Ab = Ab; g.Wb = Wb; g.bias = bias; g.C = C;
    g.M = M; g.N = N; g.Kp = Kp;
    g.kcw = up(Kp >> 6, split);
    return g;
}
static inline void tg1(const TG& g, int split)
{
    dim3 grid(up(g.N, 128), up(g.M, 128), split);
    tgemm_k<<<grid, 256, TG_SMEM>>>(g, g, 0);
}
static inline void tg2(const TG& a, const TG& b, int split)
{
    dim3 grid(up(a.N, 128), 2, split);
    tgemm_k<<<grid, 256, TG_SMEM>>>(a, b, 1);
}
static inline void wconv(const float* W, int rs, int co,
                         __nv_bfloat16* Wb, int N, int K, int Kp)
{
    wconv_k<<<up(N * Kp, 256), 256>>>(W, rs, co, Wb, N, K, Kp);
}

extern "C" void kernel_launch(void* const* d_in, const int* in_sizes, int n_in,
                              void* d_out, int out_size)
{
    (void)in_sizes; (void)n_in; (void)out_size;
    const int*   src      = (const int*)  d_in[0];
    const int*   trg      = (const int*)  d_in[1];
    const float* enc_emb  = (const float*)d_in[2];
    const float* enc_wx_f = (const float*)d_in[3];
    const float* enc_wh_f = (const float*)d_in[4];
    const float* enc_bx_f = (const float*)d_in[5];
    const float* enc_bh_f = (const float*)d_in[6];
    const float* enc_wx_b = (const float*)d_in[7];
    const float* enc_wh_b = (const float*)d_in[8];
    const float* enc_bx_b = (const float*)d_in[9];
    const float* enc_bh_b = (const float*)d_in[10];
    const float* enc_fc_w = (const float*)d_in[11];
    const float* enc_fc_b = (const float*)d_in[12];
    const float* attn_w   = (const float*)d_in[13];
    const float* attn_b   = (const float*)d_in[14];
    const float* attn_v   = (const float*)d_in[15];
    const float* dec_emb  = (const float*)d_in[16];
    const float* dec_wx   = (const float*)d_in[17];
    const float* dec_wh   = (const float*)d_in[18];
    const float* dec_bx   = (const float*)d_in[19];
    const float* dec_bh   = (const float*)d_in[20];
    const float* max_w    = (const float*)d_in[21];
    const float* max_b    = (const float*)d_in[22];
    const float* out_w    = (const float*)d_in[23];
    const float* out_b    = (const float*)d_in[24];

    cudaFuncSetAttribute(tgemm_k, cudaFuncAttributeMaxDynamicSharedMemorySize, TG_SMEM);

    float* ws = nullptr; int* inp = nullptr;
    __nv_bfloat16* wb = nullptr; __nv_bfloat16* abx = nullptr;
    cudaGetSymbolAddress((void**)&ws, g_ws);
    cudaGetSymbolAddress((void**)&inp, g_inp);
    cudaGetSymbolAddress((void**)&wb, g_wb);
    cudaGetSymbolAddress((void**)&abx, g_ab);

    float* gxf = ws + O_GXF;
    float* gxb = ws + O_GXB;
    float* enc = ws + O_ENC;
    float* ep  = ws + O_EP;
    float* pa  = ws + O_PA;
    float* pb  = ws + O_PB;
    float* pm  = ws + O_PM;
    float* hf  = ws + O_HF;
    float* hb  = ws + O_HB;
    float* hd  = ws + O_HD;
    float* out = (float*)d_out;

    __nv_bfloat16* Aemb = abx + AB_EMB;
    __nv_bfloat16* Aenc = abx + AB_ENC;
    __nv_bfloat16* Ahf  = abx + AB_HF;
    __nv_bfloat16* Ahb  = abx + AB_HB;
    __nv_bfloat16* Ahd  = abx + AB_HD;
    __nv_bfloat16* Ax   = abx + AB_X;
    __nv_bfloat16* Ami  = abx + AB_MI;
    __nv_bfloat16* Atm  = abx + AB_TM;

    // weight split conversion
    wconv(enc_wx_f, EMBD, 0,    wb + WB_EXF, 3000, EMBD, KP_EX);
    wconv(enc_wx_b, EMBD, 0,    wb + WB_EXB, 3000, EMBD, KP_EX);
    wconv(enc_wh_f, HIDN, 0,    wb + WB_WHF, 3000, HIDN, KP_WH);
    wconv(enc_wh_b, HIDN, 0,    wb + WB_WHB, 3000, HIDN, KP_WH);
    wconv(enc_fc_w, HIDN, 0,    wb + WB_FC,  1000, HIDN, KP_WH);
    wconv(attn_w,   G3,   0,    wb + WB_AWH, 1000, HIDN, KP_WH);
    wconv(attn_w,   G3,   HIDN, wb + WB_AWE, 1000, E2,   KP_EN);
    wconv(dec_wx,   DXK,  0,    wb + WB_DWX, 3000, DXK,  KP_X);
    wconv(dec_wh,   HIDN, 0,    wb + WB_DWH, 3000, HIDN, KP_WH);
    wconv(max_w,    MXK,  0,    wb + WB_MXW, 1000, MXK,  KP_MI);
    wconv(out_w,    MXO,  0,    wb + WB_OUW, 30000, MXO, KP_TM);

    cudaMemsetAsync(out, 0, (size_t)BB * OUTV * sizeof(float));

    // ---------------- Encoder ----------------
    embed_split_k<<<up(S_LEN * BB * EMBD, 256), 256>>>(enc_emb, src, Aemb, S_LEN * BB);
    tg1(mkt(Aemb, wb + WB_EXF, enc_bx_f, gxf, S_LEN * BB, G3, KP_EX, 1), 1);
    tg1(mkt(Aemb, wb + WB_EXB, enc_bx_b, gxb, S_LEN * BB, G3, KP_EX, 1), 1);

    cudaMemsetAsync(hf, 0, (size_t)BB * HIDN * sizeof(float));
    cudaMemsetAsync(hb, 0, (size_t)BB * HIDN * sizeof(float));
    cudaMemsetAsync(Ahf, 0, (size_t)BB * 3 * KP_WH * sizeof(__nv_bfloat16));
    cudaMemsetAsync(Ahb, 0, (size_t)BB * 3 * KP_WH * sizeof(__nv_bfloat16));

    for (int s = 0; s < S_LEN; s++) {
        int sb = S_LEN - 1 - s;
        TG gf = mkt(Ahf, wb + WB_WHF, nullptr, pa, BB, G3, KP_WH, 4);
        TG gb = mkt(Ahb, wb + WB_WHB, nullptr, pb, BB, G3, KP_WH, 4);
        tg2(gf, gb, 4);
        gru_gate2_k<<<up(2 * BB * HIDN, 256), 256>>>(
            gxf + (size_t)s * BB * G3, gxb + (size_t)sb * BB * G3,
            pa, pb, 4, enc_bh_f, enc_bh_b, hf, hb, Ahf, Ahb, enc, Aenc, s, sb);
    }

    tg1(mkt(Ahb, wb + WB_FC, nullptr, pa, BB, HIDN, KP_WH, 8), 8);
    finalize_tanh_hd_k<<<up(BB * HIDN, 256), 256>>>(pa, 8, enc_fc_b, hd, Ahd);
    tg1(mkt(Aenc, wb + WB_AWE, nullptr, ep, S_LEN * BB, ATTD, KP_EN, 1), 1);

    // ---------------- Decoder ----------------
    copy_inp_k<<<1, BB>>>(trg, inp);
    for (int t = 0; t < T_LEN - 1; t++) {
        tg1(mkt(Ahd, wb + WB_AWH, nullptr, pa, BB, ATTD, KP_WH, 8), 8);
        attention_k<<<BB, 256>>>(pa, ep, attn_b, attn_v, enc, dec_emb, inp, Ax, Ami);
        TG ga = mkt(Ax,  wb + WB_DWX, nullptr, pa, BB, G3, KP_X, 4);
        TG gh = mkt(Ahd, wb + WB_DWH, nullptr, pb, BB, G3, KP_WH, 4);
        tg2(ga, gh, 4);
        gru_gate_k<<<up(BB * HIDN, 256), 256>>>(pa, 4, dec_bx, pb, 4, dec_bh, hd, Ahd, Ami);
        tg1(mkt(Ami, wb + WB_MXW, nullptr, pm, BB, MX2, KP_MI, 8), 8);
        finalize_max_k<<<up(BB * MXO, 256), 256>>>(pm, 8, max_b, Atm);
        float* pred = out + (size_t)(t + 1) * BB * OUTV;
        tg1(mkt(Atm, wb + WB_OUW, out_b, pred, BB, OUTV, KP_TM, 1), 1);
        argmax_k<<<BB, 256>>>(pred, inp);
    }
}